// round 1
// baseline (speedup 1.0000x reference)
#include <cuda_runtime.h>
#include <math.h>

// Fixed problem shapes
#define BQ 4
#define HH 8
#define BH 32            // B*H
#define LL 2048
#define DD 64
#define UU 40            // top-k count
#define SK 40            // sample_k
#define NS 32            // number of key-chunks for split softmax
#define CK 64            // keys per chunk (NS*CK == LL)

// Scratch (device globals; no allocation allowed)
__device__ float g_M[BH * LL];
__device__ int   g_top[BH * UU];
__device__ float g_pm[BH * UU * NS];
__device__ float g_pl[BH * UU * NS];
__device__ float g_pacc[BH * UU * NS * DD];   // ~10.5 MB

// ---------------------------------------------------------------------------
// Kernel 1: cumsum of values along L, written to d_out.
// grid = BH, block = 1024 (64 d-lanes x 16 chunks of 128 rows)
// ---------------------------------------------------------------------------
__global__ void cumsum_kernel(const float* __restrict__ V, float* __restrict__ out) {
    const int bh    = blockIdx.x;
    const int d     = threadIdx.x & 63;
    const int chunk = threadIdx.x >> 6;     // 0..15
    const int RPC   = LL / 16;              // 128 rows per chunk
    const size_t base = (size_t)bh * LL * DD;
    const float* vp = V + base + (size_t)chunk * RPC * DD + d;

    float s = 0.f;
#pragma unroll 8
    for (int i = 0; i < RPC; i++) s += vp[(size_t)i * DD];

    __shared__ float cs[16 * 64];
    cs[chunk * 64 + d] = s;
    __syncthreads();

    float off = 0.f;
    for (int c = 0; c < chunk; c++) off += cs[c * 64 + d];

    float* op = out + base + (size_t)chunk * RPC * DD + d;
    float acc = off;
#pragma unroll 8
    for (int i = 0; i < RPC; i++) {
        acc += vp[(size_t)i * DD];
        op[(size_t)i * DD] = acc;
    }
}

// ---------------------------------------------------------------------------
// Kernel 2: sparsity metric M[bh, q] = max_s(QK_s) - sum_s(QK_s)/L
// One warp per query. grid = BH*LL/8 blocks of 256 threads (8 warps).
// ---------------------------------------------------------------------------
__global__ void m_kernel(const float* __restrict__ Q, const float* __restrict__ K,
                         const int* __restrict__ idxs) {
    const int w    = blockIdx.x * 8 + (threadIdx.x >> 5);
    const int lane = threadIdx.x & 31;
    const int bh   = w >> 11;        // / 2048
    const int q    = w & (LL - 1);
    const size_t base = (size_t)bh * LL * DD;

    const float q0 = __ldg(Q + base + (size_t)q * DD + lane);
    const float q1 = __ldg(Q + base + (size_t)q * DD + 32 + lane);

    float mx = -INFINITY, sm = 0.f;
    const int* ip = idxs + q * SK;
#pragma unroll 4
    for (int s = 0; s < SK; s++) {
        const int idx = __ldg(ip + s);
        const float k0 = __ldg(K + base + (size_t)idx * DD + lane);
        const float k1 = __ldg(K + base + (size_t)idx * DD + 32 + lane);
        float p = q0 * k0 + q1 * k1;
#pragma unroll
        for (int off = 16; off; off >>= 1) p += __shfl_xor_sync(0xffffffffu, p, off);
        mx = fmaxf(mx, p);
        sm += p;
    }
    if (lane == 0) g_M[bh * LL + q] = mx - sm * (1.0f / (float)LL);
}

// ---------------------------------------------------------------------------
// Kernel 3: top-40 indices of M per (b,h). grid = BH, block = 256.
// ---------------------------------------------------------------------------
__global__ void topk_kernel() {
    const int bh = blockIdx.x;
    const int t  = threadIdx.x;
    __shared__ float sM[LL];
    __shared__ float wv[8];
    __shared__ int   wi[8];

    for (int i = t; i < LL; i += 256) sM[i] = g_M[bh * LL + i];
    __syncthreads();

    for (int it = 0; it < UU; it++) {
        float bv = -INFINITY; int bi = 0x7fffffff;
        for (int i = t; i < LL; i += 256) {
            float v = sM[i];
            if (v > bv || (v == bv && i < bi)) { bv = v; bi = i; }
        }
#pragma unroll
        for (int off = 16; off; off >>= 1) {
            float ov = __shfl_xor_sync(0xffffffffu, bv, off);
            int   oi = __shfl_xor_sync(0xffffffffu, bi, off);
            if (ov > bv || (ov == bv && oi < bi)) { bv = ov; bi = oi; }
        }
        if ((t & 31) == 0) { wv[t >> 5] = bv; wi[t >> 5] = bi; }
        __syncthreads();
        if (t == 0) {
            float fb = wv[0]; int fi = wi[0];
            for (int ww = 1; ww < 8; ww++)
                if (wv[ww] > fb || (wv[ww] == fb && wi[ww] < fi)) { fb = wv[ww]; fi = wi[ww]; }
            g_top[bh * UU + it] = fi;
            sM[fi] = -INFINITY;
        }
        __syncthreads();
    }
}

// ---------------------------------------------------------------------------
// Kernel 4: split-K attention partials.
// grid = BH*NS, block = CK (=64) threads. Thread t = key t (score phase),
// thread t = dim t (PV phase).
// ---------------------------------------------------------------------------
__global__ void attn_partial_kernel(const float* __restrict__ Q,
                                    const float* __restrict__ K,
                                    const float* __restrict__ V) {
    const int bh = blockIdx.x / NS;
    const int c  = blockIdx.x % NS;
    const int t    = threadIdx.x;     // 0..63
    const int lane = t & 31;
    const int wid  = t >> 5;          // 0..1
    const size_t base = (size_t)bh * LL * DD;
    const int k0 = c * CK;

    __shared__ float Ks[CK][68];      // stride-68 => conflict-free LDS.128
    __shared__ float Vs[CK][DD];
    __shared__ float Qs[DD];
    __shared__ float ps[CK];
    __shared__ float redm[2], redl[2];

    // Load K/V chunk (64 rows x 16 float4 each)
    for (int i = t; i < CK * 16; i += CK) {
        const int r = i >> 4, j = i & 15;
        float4 kv = __ldg((const float4*)(K + base + (size_t)(k0 + r) * DD + j * 4));
        *(float4*)&Ks[r][j * 4] = kv;
        float4 vv = __ldg((const float4*)(V + base + (size_t)(k0 + r) * DD + j * 4));
        *(float4*)&Vs[r][j * 4] = vv;
    }
    __syncthreads();

    for (int u = 0; u < UU; u++) {
        const int pos = g_top[bh * UU + u];
        const int pi  = (bh * UU + u) * NS + c;
        if (k0 > pos) {   // fully masked chunk (uniform branch)
            if (t == 0) { g_pm[pi] = -INFINITY; g_pl[pi] = 0.f; }
            continue;
        }
        __syncthreads();   // protect Qs/ps from previous iteration readers
        if (t < 16)
            *(float4*)&Qs[t * 4] = __ldg((const float4*)(Q + base + (size_t)pos * DD + t * 4));
        __syncthreads();

        // score for key (k0 + t)
        const int kg = k0 + t;
        float s;
        if (kg <= pos) {
            float acc = 0.f;
#pragma unroll
            for (int j = 0; j < 16; j++) {
                float4 kv = *(float4*)&Ks[t][j * 4];
                float4 qv = *(float4*)&Qs[j * 4];
                acc += kv.x * qv.x + kv.y * qv.y + kv.z * qv.z + kv.w * qv.w;
            }
            s = acc * 0.125f;      // 1/sqrt(64)
        } else {
            s = -INFINITY;
        }

        // block max (2 warps)
        float m = s;
#pragma unroll
        for (int off = 16; off; off >>= 1) m = fmaxf(m, __shfl_xor_sync(0xffffffffu, m, off));
        if (lane == 0) redm[wid] = m;
        __syncthreads();
        m = fmaxf(redm[0], redm[1]);   // finite: key k0 <= pos is unmasked

        float p = (kg <= pos) ? __expf(s - m) : 0.f;
        ps[t] = p;
        float l = p;
#pragma unroll
        for (int off = 16; off; off >>= 1) l += __shfl_xor_sync(0xffffffffu, l, off);
        if (lane == 0) redl[wid] = l;
        __syncthreads();               // also makes ps visible
        l = redl[0] + redl[1];

        // PV: thread t = dim t, sum over all CK keys
        float a = 0.f;
#pragma unroll
        for (int k = 0; k < CK; k++) a += ps[k] * Vs[k][t];
        g_pacc[(size_t)pi * DD + t] = a;
        if (t == 0) { g_pm[pi] = m; g_pl[pi] = l; }
    }
}

// ---------------------------------------------------------------------------
// Kernel 5: combine partials (log-sum-exp) and scatter into d_out.
// grid = BH*UU, block = 64 (thread = dim).
// ---------------------------------------------------------------------------
__global__ void combine_kernel(float* __restrict__ out) {
    const int bhu = blockIdx.x;
    const int t   = threadIdx.x;
    const int bh  = bhu / UU;
    const int pos = g_top[bhu];

    float mx = -INFINITY;
#pragma unroll
    for (int c = 0; c < NS; c++) mx = fmaxf(mx, g_pm[bhu * NS + c]);

    float Ls = 0.f, acc = 0.f;
#pragma unroll
    for (int c = 0; c < NS; c++) {
        const float plv = g_pl[bhu * NS + c];
        if (plv > 0.f) {
            const float w = __expf(g_pm[bhu * NS + c] - mx);
            Ls  += plv * w;
            acc += w * g_pacc[(size_t)(bhu * NS + c) * DD + t];
        }
    }
    out[(size_t)bh * LL * DD + (size_t)pos * DD + t] = acc / Ls;
}

// ---------------------------------------------------------------------------
extern "C" void kernel_launch(void* const* d_in, const int* in_sizes, int n_in,
                              void* d_out, int out_size) {
    const float* Q   = (const float*)d_in[0];
    const float* K   = (const float*)d_in[1];
    const float* V   = (const float*)d_in[2];
    const int*   idx = (const int*)d_in[3];
    float* out = (float*)d_out;

    cumsum_kernel<<<BH, 1024>>>(V, out);
    m_kernel<<<BH * LL / 8, 256>>>(Q, K, idx);
    topk_kernel<<<BH, 256>>>();
    attn_partial_kernel<<<BH * NS, CK>>>(Q, K, V);
    combine_kernel<<<BH * UU, DD>>>(out);
}